// round 3
// baseline (speedup 1.0000x reference)
#include <cuda_runtime.h>
#include <cstdint>

#define H 32
#define EPSV 1e-5f
#define N_MAX 10016
#define M_MAX 262144
#define NOUT_MAX 4000000
#define FULLMASK 0xffffffffu

// ---------------- scratch (device globals; no runtime allocation) ----------
__device__ float g_degcnt[N_MAX];
__device__ float g_dinv[N_MAX];
__device__ float g_rdeg[N_MAX];
__device__ float g_h[N_MAX * H];      // x@W (pre-aggregation) for current GCN layer
__device__ float g_agg[N_MAX * H];    // layer-1 aggregation target
__device__ float g_agg2[N_MAX * H];   // layer-2 aggregation target
__device__ float g_x[N_MAX * H];      // final node features after layer 2
__device__ float g_xe[M_MAX * H];
__device__ float g_mul[M_MAX * H];
__device__ float g_bmm[(size_t)NOUT_MAX * H];
__device__ float g_colsum[H];
__device__ float g_colsq[H];
__device__ float g_mean[H];
__device__ float g_invstd[H];
// Gram accumulators for mlp3 GraphNorm stats
__device__ float g_gram[H * H];   // G[k][l] = sum_rows bmm_k * bmm_l
__device__ float g_gs[H];         // sum_rows bmm_k
__device__ float g_gw[H];         // sum_rows is_edge * bmm_k
__device__ float g_gie[2];        // [0] = sum is_edge, [1] = sum is_edge^2

__device__ __forceinline__ void red_add_f4(float* addr, float4 v) {
#if __CUDA_ARCH__ >= 900
    atomicAdd(reinterpret_cast<float4*>(addr), v);
#else
    atomicAdd(addr + 0, v.x);
    atomicAdd(addr + 1, v.y);
    atomicAdd(addr + 2, v.z);
    atomicAdd(addr + 3, v.w);
#endif
}

// ---------------- zero kernels ----------------------------------------------
__global__ void k_zero_all(int n_nodes, long long bmm4) {
    long long i = (long long)blockIdx.x * blockDim.x + threadIdx.x;
    long long stride = (long long)gridDim.x * blockDim.x;
    float4 z = make_float4(0.f, 0.f, 0.f, 0.f);
    float4* p = reinterpret_cast<float4*>(g_bmm);
    for (long long idx = i; idx < bmm4; idx += stride) p[idx] = z;
    int tot = n_nodes * H;
    for (long long idx = i; idx < tot; idx += stride) {
        g_agg[idx] = 0.f;
        g_agg2[idx] = 0.f;
    }
    for (long long idx = i; idx < n_nodes; idx += stride) g_degcnt[idx] = 0.f;
    if (i < H) { g_colsum[i] = 0.f; g_colsq[i] = 0.f; g_gs[i] = 0.f; g_gw[i] = 0.f; }
    if (i < H * H) g_gram[i] = 0.f;
    if (i < 2) g_gie[i] = 0.f;
}

// ---------------- degree / normalization ------------------------------------
__global__ void k_deg(const int* __restrict__ dst, int m) {
    int e = blockIdx.x * blockDim.x + threadIdx.x;
    if (e < m) atomicAdd(&g_degcnt[dst[e]], 1.f);
}

__global__ void k_dinv(int n) {
    int i = blockIdx.x * blockDim.x + threadIdx.x;
    if (i < n) {
        float d = g_degcnt[i] + 1.f;
        g_dinv[i] = rsqrtf(d);
        g_rdeg[i] = 1.f / d;
    }
}

// ---------------- node tower -------------------------------------------------
__global__ void k_embed_gemm(const float* __restrict__ emb,
                             const int* __restrict__ x_nodes,
                             const float* __restrict__ w, int n) {
    __shared__ float ws[H * H];
    for (int i = threadIdx.x; i < H * H; i += blockDim.x) ws[i] = w[i];
    __syncthreads();
    int lane = threadIdx.x & 31;
    int row = (blockIdx.x * blockDim.x + threadIdx.x) >> 5;
    if (row >= n) return;
    float v = emb[x_nodes[row] * H + lane];
    float acc = 0.f;
#pragma unroll
    for (int k = 0; k < H; k++)
        acc = fmaf(__shfl_sync(FULLMASK, v, k), ws[k * H + lane], acc);
    g_h[row * H + lane] = acc;
}

// agg[dst] += h[src] * dinv[src]*dinv[dst]   (8 threads per edge, float4 atomics)
__global__ void k_agg(const int* __restrict__ src, const int* __restrict__ dst,
                      float* __restrict__ agg, int m) {
    int idx = blockIdx.x * blockDim.x + threadIdx.x;
    int sub = idx & 7;
    int e = idx >> 3;
    if (e >= m) return;
    int s = src[e], d = dst[e];
    float en = g_dinv[s] * g_dinv[d];
    const float4 h4 = *reinterpret_cast<const float4*>(&g_h[s * H + sub * 4]);
    float4 p = make_float4(h4.x * en, h4.y * en, h4.z * en, h4.w * en);
    red_add_f4(&agg[d * H + sub * 4], p);
}

// y = agg + h/deg + b  (in place) + accumulate column sums/sumsq
__global__ void k_post(const float* __restrict__ bias, float* __restrict__ agg, int n) {
    int lane = threadIdx.x & 31;
    int wid = threadIdx.x >> 5;
    int gw = (blockIdx.x * blockDim.x + threadIdx.x) >> 5;
    int nwarps = (gridDim.x * blockDim.x) >> 5;
    float b = bias[lane];
    float sum = 0.f, sq = 0.f;
    for (int row = gw; row < n; row += nwarps) {
        float y = agg[row * H + lane] + g_h[row * H + lane] * g_rdeg[row] + b;
        agg[row * H + lane] = y;
        sum += y;
        sq += y * y;
    }
    __shared__ float s_sum[8][32];
    __shared__ float s_sq[8][32];
    s_sum[wid][lane] = sum;
    s_sq[wid][lane] = sq;
    __syncthreads();
    if (threadIdx.x < 32) {
        float ts = 0.f, tq = 0.f;
#pragma unroll
        for (int w = 0; w < 8; w++) { ts += s_sum[w][threadIdx.x]; tq += s_sq[w][threadIdx.x]; }
        atomicAdd(&g_colsum[threadIdx.x], ts);
        atomicAdd(&g_colsq[threadIdx.x], tq);
    }
}

// mean / invstd from accumulated sums; reset accumulators.
__global__ void k_statsfin(const float* __restrict__ ms, float inv_n) {
    int c = threadIdx.x;
    if (c < H) {
        float mean = g_colsum[c] * inv_n;
        float m2 = g_colsq[c] * inv_n;
        float msv = ms[c];
        float var = m2 - msv * (2.f - msv) * mean * mean;
        g_mean[c] = mean;
        g_invstd[c] = rsqrtf(var + EPSV);
        g_colsum[c] = 0.f;
        g_colsq[c] = 0.f;
    }
}

// x1 = relu(gnorm(y));  h2 = x1 @ W2  -> g_h (overwrite)
__global__ void k_norm_gemm(const float* __restrict__ gnw, const float* __restrict__ gnb,
                            const float* __restrict__ ms, const float* __restrict__ w2,
                            const float* __restrict__ agg, int n) {
    __shared__ float ws[H * H];
    for (int i = threadIdx.x; i < H * H; i += blockDim.x) ws[i] = w2[i];
    __syncthreads();
    int lane = threadIdx.x & 31;
    int row = (blockIdx.x * blockDim.x + threadIdx.x) >> 5;
    if (row >= n) return;
    float y = agg[row * H + lane];
    float xv = gnw[lane] * (y - ms[lane] * g_mean[lane]) * g_invstd[lane] + gnb[lane];
    xv = fmaxf(xv, 0.f);
    float acc = 0.f;
#pragma unroll
    for (int k = 0; k < H; k++)
        acc = fmaf(__shfl_sync(FULLMASK, xv, k), ws[k * H + lane], acc);
    g_h[row * H + lane] = acc;
}

// x = relu(gnorm(y)) -> g_x
__global__ void k_norm_only(const float* __restrict__ gnw, const float* __restrict__ gnb,
                            const float* __restrict__ ms, const float* __restrict__ agg, int n) {
    int lane = threadIdx.x & 31;
    int row = (blockIdx.x * blockDim.x + threadIdx.x) >> 5;
    if (row >= n) return;
    float y = agg[row * H + lane];
    float xv = gnw[lane] * (y - ms[lane] * g_mean[lane]) * g_invstd[lane] + gnb[lane];
    g_x[row * H + lane] = fmaxf(xv, 0.f);
}

// ---------------- edge MLPs ---------------------------------------------------
__global__ void k_edge_mlp(const int* __restrict__ src, const int* __restrict__ dst,
                           const float* __restrict__ w1, const float* __restrict__ b1,
                           const float* __restrict__ w2, const float* __restrict__ b2, int m) {
    __shared__ float w1s[2 * H * H];
    __shared__ float w2s[2 * H * H];
    for (int i = threadIdx.x; i < 2 * H * H; i += blockDim.x) { w1s[i] = w1[i]; w2s[i] = w2[i]; }
    __syncthreads();
    int lane = threadIdx.x & 31;
    int e = (blockIdx.x * blockDim.x + threadIdx.x) >> 5;
    if (e >= m) return;
    int s = src[e], d = dst[e];
    float xs = g_x[s * H + lane];
    float xd = g_x[d * H + lane];
    float a1 = b1[lane], a2 = b2[lane];
#pragma unroll
    for (int k = 0; k < H; k++) {
        float v = __shfl_sync(FULLMASK, xs, k);
        a1 = fmaf(v, w1s[k * H + lane], a1);
        a2 = fmaf(v, w2s[k * H + lane], a2);
    }
#pragma unroll
    for (int k = 0; k < H; k++) {
        float v = __shfl_sync(FULLMASK, xd, k);
        a1 = fmaf(v, w1s[(H + k) * H + lane], a1);
        a2 = fmaf(v, w2s[(H + k) * H + lane], a2);
    }
    g_xe[e * H + lane] = fmaxf(a1, 0.f);
    g_mul[e * H + lane] = fmaxf(a2, 0.f);
}

// ---------------- sparse-sparse bmm scatter (8 threads/triple, float4 atomics) --
__global__ void k_scatter(const int* __restrict__ tri_a, const int* __restrict__ tri_b,
                          const int* __restrict__ tri_seg, int T) {
    int idx = blockIdx.x * blockDim.x + threadIdx.x;
    int sub = idx & 7;
    int t = idx >> 3;
    if (t >= T) return;
    int a = tri_a[t], b = tri_b[t], sg = tri_seg[t];
    const float4 xe4 = *reinterpret_cast<const float4*>(&g_xe[a * H + sub * 4]);
    const float4 mu4 = *reinterpret_cast<const float4*>(&g_mul[b * H + sub * 4]);
    float4 p = make_float4(xe4.x * mu4.x, xe4.y * mu4.y, xe4.z * mu4.z, xe4.w * mu4.w);
    red_add_f4(&g_bmm[(size_t)sg * H + sub * 4], p);
}

// ---------------- Gram accumulation for mlp3 GraphNorm stats -----------------
// G = sum_rows v v^T where v = bmm row (32), plus side sums for is_edge & ones.
// Lane (ly=lane>>2, lx=lane&3) owns the 4x8 tile G[ly*4+i][lx*8+j].
__global__ void __launch_bounds__(256) k_gram(const float* __restrict__ is_edge, int n) {
    int lane = threadIdx.x & 31;
    int gw = (blockIdx.x * blockDim.x + threadIdx.x) >> 5;
    int nwarps = (gridDim.x * blockDim.x) >> 5;
    int ly = lane >> 2;
    int lx = lane & 3;
    float acc[4][8];
#pragma unroll
    for (int i = 0; i < 4; i++)
#pragma unroll
        for (int j = 0; j < 8; j++) acc[i][j] = 0.f;
    float s = 0.f, w = 0.f, sie = 0.f, sie2 = 0.f;

    int row = gw;
    for (; row + nwarps < n; row += 2 * nwarps) {
        int r0 = row, r1 = row + nwarps;
        float v0 = g_bmm[(size_t)r0 * H + lane];
        float v1 = g_bmm[(size_t)r1 * H + lane];
        float ie0 = __ldg(&is_edge[r0]);
        float ie1 = __ldg(&is_edge[r1]);
        float ra0[4], ra1[4], cb0[8], cb1[8];
#pragma unroll
        for (int i = 0; i < 4; i++) {
            ra0[i] = __shfl_sync(FULLMASK, v0, ly * 4 + i);
            ra1[i] = __shfl_sync(FULLMASK, v1, ly * 4 + i);
        }
#pragma unroll
        for (int j = 0; j < 8; j++) {
            cb0[j] = __shfl_sync(FULLMASK, v0, lx * 8 + j);
            cb1[j] = __shfl_sync(FULLMASK, v1, lx * 8 + j);
        }
#pragma unroll
        for (int i = 0; i < 4; i++)
#pragma unroll
            for (int j = 0; j < 8; j++) {
                acc[i][j] = fmaf(ra0[i], cb0[j], acc[i][j]);
                acc[i][j] = fmaf(ra1[i], cb1[j], acc[i][j]);
            }
        s += v0 + v1;
        w = fmaf(ie0, v0, fmaf(ie1, v1, w));
        sie += ie0 + ie1;
        sie2 = fmaf(ie0, ie0, fmaf(ie1, ie1, sie2));
    }
    for (; row < n; row += nwarps) {
        float v0 = g_bmm[(size_t)row * H + lane];
        float ie0 = __ldg(&is_edge[row]);
        float ra0[4], cb0[8];
#pragma unroll
        for (int i = 0; i < 4; i++) ra0[i] = __shfl_sync(FULLMASK, v0, ly * 4 + i);
#pragma unroll
        for (int j = 0; j < 8; j++) cb0[j] = __shfl_sync(FULLMASK, v0, lx * 8 + j);
#pragma unroll
        for (int i = 0; i < 4; i++)
#pragma unroll
            for (int j = 0; j < 8; j++) acc[i][j] = fmaf(ra0[i], cb0[j], acc[i][j]);
        s += v0;
        w = fmaf(ie0, v0, w);
        sie += ie0;
        sie2 = fmaf(ie0, ie0, sie2);
    }
    // reduce: direct global atomics (34 per lane, spread addresses)
#pragma unroll
    for (int i = 0; i < 4; i++)
#pragma unroll
        for (int j = 0; j < 8; j++)
            atomicAdd(&g_gram[(ly * 4 + i) * H + lx * 8 + j], acc[i][j]);
    atomicAdd(&g_gs[lane], s);
    atomicAdd(&g_gw[lane], w);
    if (lane == 0) {
        atomicAdd(&g_gie[0], sie);
        atomicAdd(&g_gie[1], sie2);
    }
}

// Finisher: mean/invstd for gn3 from Gram matrix.
// h_j = sum_{k<33} v_k W[k][j] + b_j. Augmented v' = [bmm(32), is_edge, 1].
__global__ void k_gramfin(const float* __restrict__ w3, const float* __restrict__ b3,
                          const float* __restrict__ ms, float fn) {
    int j = threadIdx.x;
    if (j >= H) return;
    float Wc[34];
#pragma unroll 1
    for (int k = 0; k < 33; k++) Wc[k] = w3[k * H + j];
    Wc[33] = b3[j];
    float inv_n = 1.f / fn;
    // G'(k,l) accessor values
    double q = 0.0;
    for (int k = 0; k < 34; k++) {
        double rowdot = 0.0;
        for (int l = 0; l < 34; l++) {
            float gkl;
            if (k < 32) {
                if (l < 32) gkl = g_gram[k * H + l];
                else if (l == 32) gkl = g_gw[k];
                else gkl = g_gs[k];
            } else if (k == 32) {
                if (l < 32) gkl = g_gw[l];
                else if (l == 32) gkl = g_gie[1];
                else gkl = g_gie[0];
            } else { // k == 33
                if (l < 32) gkl = g_gs[l];
                else if (l == 32) gkl = g_gie[0];
                else gkl = fn;
            }
            rowdot += (double)gkl * (double)Wc[l];
        }
        q += (double)Wc[k] * rowdot;
    }
    // mean_j = (1/n) sum_k G'(33,k) Wc[k]
    double msum = 0.0;
    for (int k = 0; k < 32; k++) msum += (double)g_gs[k] * (double)Wc[k];
    msum += (double)g_gie[0] * (double)Wc[32];
    msum += (double)fn * (double)Wc[33];
    float mean = (float)(msum * (double)inv_n);
    float m2 = (float)(q * (double)inv_n);
    float msv = ms[j];
    float var = m2 - msv * (2.f - msv) * mean * mean;
    g_mean[j] = mean;
    g_invstd[j] = rsqrtf(var + EPSV);
}

// ---------------- final query kernel ------------------------------------------
__device__ __forceinline__ float compute_xo(int row, int lane, const float* ws,
                                            const float* __restrict__ is_edge,
                                            const float* __restrict__ b3,
                                            const float* __restrict__ gn3w,
                                            const float* __restrict__ gn3b,
                                            const float* __restrict__ gn3ms) {
    float v = g_bmm[(size_t)row * H + lane];
    float acc = fmaf(is_edge[row], ws[32 * H + lane], b3[lane]);
#pragma unroll
    for (int k = 0; k < H; k++)
        acc = fmaf(__shfl_sync(FULLMASK, v, k), ws[k * H + lane], acc);
    float xo = gn3w[lane] * (acc - gn3ms[lane] * g_mean[lane]) * g_invstd[lane] + gn3b[lane];
    return fmaxf(xo, 0.f);
}

__global__ void k_final(const int* __restrict__ pred_idx, const int* __restrict__ trans_perm,
                        const float* __restrict__ pred_mask, const int* __restrict__ pos,
                        const float* __restrict__ is_edge,
                        const float* __restrict__ w3, const float* __restrict__ b3,
                        const float* __restrict__ gn3w, const float* __restrict__ gn3b,
                        const float* __restrict__ gn3ms,
                        const float* __restrict__ lw, const float* __restrict__ lb,
                        float* __restrict__ out, int P) {
    __shared__ float ws[33 * H];
    for (int i = threadIdx.x; i < 33 * H; i += blockDim.x) ws[i] = w3[i];
    __syncthreads();
    int lane = threadIdx.x & 31;
    int p = (blockIdx.x * blockDim.x + threadIdx.x) >> 5;
    if (p >= P) return;
    int r = pred_idx[p];
    int rt = trans_perm[r];
    float mask = pred_mask[p];
    float xo_r = compute_xo(r, lane, ws, is_edge, b3, gn3w, gn3b, gn3ms);
    float xo_t = compute_xo(rt, lane, ws, is_edge, b3, gn3w, gn3b, gn3ms);
    int i0 = pos[2 * p], j0 = pos[2 * p + 1];
    float xx = g_x[i0 * H + lane] * g_x[j0 * H + lane];
    float part = xo_r * xo_t * mask * lw[lane] + xx * lw[H + lane];
#pragma unroll
    for (int off = 16; off; off >>= 1) part += __shfl_down_sync(FULLMASK, part, off);
    if (lane == 0) out[p] = part + lb[0];
}

// ---------------- launch ------------------------------------------------------
extern "C" void kernel_launch(void* const* d_in, const int* in_sizes, int n_in,
                              void* d_out, int out_size) {
    const float* emb     = (const float*)d_in[0];
    const float* gcn1_w  = (const float*)d_in[1];
    const float* gcn1_b  = (const float*)d_in[2];
    const float* gn1_w   = (const float*)d_in[3];
    const float* gn1_b   = (const float*)d_in[4];
    const float* gn1_ms  = (const float*)d_in[5];
    const float* gcn2_w  = (const float*)d_in[6];
    const float* gcn2_b  = (const float*)d_in[7];
    const float* gn2_w   = (const float*)d_in[8];
    const float* gn2_b   = (const float*)d_in[9];
    const float* gn2_ms  = (const float*)d_in[10];
    const float* mlp1_w  = (const float*)d_in[11];
    const float* mlp1_b  = (const float*)d_in[12];
    const float* mlp2_w  = (const float*)d_in[13];
    const float* mlp2_b  = (const float*)d_in[14];
    const float* mlp3_w  = (const float*)d_in[15];
    const float* mlp3_b  = (const float*)d_in[16];
    const float* gn3_w   = (const float*)d_in[17];
    const float* gn3_b   = (const float*)d_in[18];
    const float* gn3_ms  = (const float*)d_in[19];
    const float* lind_w  = (const float*)d_in[20];
    const float* lind_b  = (const float*)d_in[21];
    const float* is_edge = (const float*)d_in[22];
    const float* pred_mask = (const float*)d_in[23];
    const int* x_nodes   = (const int*)d_in[24];
    const int* ei        = (const int*)d_in[25];
    const int* pos       = (const int*)d_in[26];
    const int* tri_a     = (const int*)d_in[27];
    const int* tri_b     = (const int*)d_in[28];
    const int* tri_seg   = (const int*)d_in[29];
    const int* trans_perm= (const int*)d_in[30];
    const int* pred_idx  = (const int*)d_in[31];

    int N     = in_sizes[24];
    int m     = in_sizes[25] / 2;
    int n_out = in_sizes[22];
    int T     = in_sizes[27];
    int P     = in_sizes[23];

    const int* src = ei;
    const int* dst = ei + m;

    int nodeWarpBlocks = (N * H + 255) / 256;
    int edgeVecBlocks = (int)(((long long)m * 8 + 255) / 256);
    int edgeWarpBlocks = (int)(((long long)m * H + 255) / 256);
    int triVecBlocks  = (int)(((long long)T * 8 + 255) / 256);
    int queryWarpBlocks = (P * H + 255) / 256;

    long long bmm4 = ((long long)n_out * H) / 4;
    k_zero_all<<<2048, 256>>>(N, bmm4);

    // degrees
    k_deg<<<(m + 255) / 256, 256>>>(dst, m);
    k_dinv<<<(N + 255) / 256, 256>>>(N);

    // GCN layer 1
    k_embed_gemm<<<nodeWarpBlocks, 256>>>(emb, x_nodes, gcn1_w, N);
    k_agg<<<edgeVecBlocks, 256>>>(src, dst, g_agg, m);
    k_post<<<120, 256>>>(gcn1_b, g_agg, N);
    k_statsfin<<<1, 32>>>(gn1_ms, 1.f / (float)N);
    k_norm_gemm<<<nodeWarpBlocks, 256>>>(gn1_w, gn1_b, gn1_ms, gcn2_w, g_agg, N);

    // GCN layer 2
    k_agg<<<edgeVecBlocks, 256>>>(src, dst, g_agg2, m);
    k_post<<<120, 256>>>(gcn2_b, g_agg2, N);
    k_statsfin<<<1, 32>>>(gn2_ms, 1.f / (float)N);
    k_norm_only<<<nodeWarpBlocks, 256>>>(gn2_w, gn2_b, gn2_ms, g_agg2, N);

    // edge MLPs
    k_edge_mlp<<<edgeWarpBlocks, 256>>>(src, dst, mlp1_w, mlp1_b, mlp2_w, mlp2_b, m);

    // sparse-sparse bmm (vector atomics)
    k_scatter<<<triVecBlocks, 256>>>(tri_a, tri_b, tri_seg, T);

    // mlp3 GraphNorm statistics via Gram matrix (no per-row matvec)
    k_gram<<<1184, 256>>>(is_edge, n_out);
    k_gramfin<<<1, 32>>>(mlp3_w, mlp3_b, gn3_ms, (float)n_out);

    // final query kernel
    k_final<<<queryWarpBlocks, 256>>>(pred_idx, trans_perm, pred_mask, pos, is_edge,
                                      mlp3_w, mlp3_b, gn3_w, gn3_b, gn3_ms,
                                      lind_w, lind_b, (float*)d_out, P);
}

// round 4
// speedup vs baseline: 1.4390x; 1.4390x over previous
#include <cuda_runtime.h>
#include <cstdint>

#define H 32
#define EPSV 1e-5f
#define N_MAX 10016
#define M_MAX 262144
#define NOUT_MAX 4000000
#define FULLMASK 0xffffffffu

// ---------------- scratch (device globals; no runtime allocation) ----------
__device__ float g_degcnt[N_MAX];
__device__ float g_h[N_MAX * H];
__device__ float g_agg[N_MAX * H];
__device__ float g_agg2[N_MAX * H];
__device__ float g_x[N_MAX * H];
__device__ float g_xe[M_MAX * H];
__device__ float g_mul[M_MAX * H];
__device__ float g_bmm[(size_t)NOUT_MAX * H];
__device__ float g_colsum[H];
__device__ float g_colsq[H];
__device__ float g_mean[H];
__device__ float g_invstd[H];
__device__ float g_gram[H * H];   // G[k][l] = sum_rows bmm_k * bmm_l
__device__ float g_gs[H];         // sum_rows bmm_k
__device__ float g_gw[H];         // sum_rows is_edge * bmm_k
__device__ int   g_tlo[N_MAX + 1];
__device__ float g_w1t[2048];     // transposed/packed mlp1_w: float idx k4*128 + j*4 + c
__device__ float g_w2t[2048];

__device__ __forceinline__ void red_add_f4(float* addr, float4 v) {
#if __CUDA_ARCH__ >= 900
    atomicAdd(reinterpret_cast<float4*>(addr), v);
#else
    atomicAdd(addr + 0, v.x);
    atomicAdd(addr + 1, v.y);
    atomicAdd(addr + 2, v.z);
    atomicAdd(addr + 3, v.w);
#endif
}

// ---------------- small zero + weight prep -----------------------------------
__global__ void k_zero_small(int n_nodes) {
    int i = blockIdx.x * blockDim.x + threadIdx.x;
    int stride = gridDim.x * blockDim.x;
    int tot = n_nodes * H;
    for (int idx = i; idx < tot; idx += stride) {
        g_agg[idx] = 0.f;
        g_agg2[idx] = 0.f;
    }
    for (int idx = i; idx < n_nodes; idx += stride) g_degcnt[idx] = 0.f;
    if (i < H) { g_colsum[i] = 0.f; g_colsq[i] = 0.f; g_gs[i] = 0.f; g_gw[i] = 0.f; }
    if (i < H * H) g_gram[i] = 0.f;
}

__global__ void k_wprep(const float* __restrict__ w1, const float* __restrict__ w2) {
    int idx = blockIdx.x * blockDim.x + threadIdx.x;
    if (idx >= 2048) return;
    int c = idx & 3;
    int j = (idx >> 2) & 31;
    int k4 = idx >> 7;
    g_w1t[idx] = w1[(k4 * 4 + c) * 32 + j];
    g_w2t[idx] = w2[(k4 * 4 + c) * 32 + j];
}

// ---------------- degrees -----------------------------------------------------
__global__ void k_deg(const int* __restrict__ dst, int m) {
    int e = blockIdx.x * blockDim.x + threadIdx.x;
    if (e < m) atomicAdd(&g_degcnt[dst[e]], 1.f);
}

// per-node triple range start: first t with src[tri_a[t]] >= i
__global__ void k_bounds(const int* __restrict__ src, const int* __restrict__ tri_a,
                         int n, int T) {
    int i = blockIdx.x * blockDim.x + threadIdx.x;
    if (i > n) return;
    int lo = 0, hi = T;
    while (lo < hi) {
        int mid = (lo + hi) >> 1;
        int node = src[tri_a[mid]];
        if (node < i) lo = mid + 1; else hi = mid;
    }
    g_tlo[i] = lo;
}

// ---------------- node tower -------------------------------------------------
__global__ void k_embed_gemm(const float* __restrict__ emb,
                             const int* __restrict__ x_nodes,
                             const float* __restrict__ w, int n) {
    __shared__ float ws[H * H];
    for (int i = threadIdx.x; i < H * H; i += blockDim.x) ws[i] = w[i];
    __syncthreads();
    int lane = threadIdx.x & 31;
    int row = (blockIdx.x * blockDim.x + threadIdx.x) >> 5;
    if (row >= n) return;
    float v = emb[x_nodes[row] * H + lane];
    float acc = 0.f;
#pragma unroll
    for (int k = 0; k < H; k++)
        acc = fmaf(__shfl_sync(FULLMASK, v, k), ws[k * H + lane], acc);
    g_h[row * H + lane] = acc;
}

// agg[dst] += h[src] * rsqrt(deg_s)*rsqrt(deg_d)  (8 threads/edge, float4 atomics)
__global__ void k_agg(const int* __restrict__ src, const int* __restrict__ dst,
                      float* __restrict__ agg, int m) {
    int idx = blockIdx.x * blockDim.x + threadIdx.x;
    int sub = idx & 7;
    int e = idx >> 3;
    if (e >= m) return;
    int s = src[e], d = dst[e];
    float en = rsqrtf(g_degcnt[s] + 1.f) * rsqrtf(g_degcnt[d] + 1.f);
    const float4 h4 = *reinterpret_cast<const float4*>(&g_h[s * H + sub * 4]);
    float4 p = make_float4(h4.x * en, h4.y * en, h4.z * en, h4.w * en);
    red_add_f4(&agg[d * H + sub * 4], p);
}

// y = agg + h/deg + b  (in place) + column sums/sumsq
__global__ void k_post(const float* __restrict__ bias, float* __restrict__ agg, int n) {
    int lane = threadIdx.x & 31;
    int wid = threadIdx.x >> 5;
    int gw = (blockIdx.x * blockDim.x + threadIdx.x) >> 5;
    int nwarps = (gridDim.x * blockDim.x) >> 5;
    float b = bias[lane];
    float sum = 0.f, sq = 0.f;
    for (int row = gw; row < n; row += nwarps) {
        float rdeg = 1.f / (g_degcnt[row] + 1.f);
        float y = agg[row * H + lane] + g_h[row * H + lane] * rdeg + b;
        agg[row * H + lane] = y;
        sum += y;
        sq += y * y;
    }
    __shared__ float s_sum[8][32];
    __shared__ float s_sq[8][32];
    s_sum[wid][lane] = sum;
    s_sq[wid][lane] = sq;
    __syncthreads();
    if (threadIdx.x < 32) {
        float ts = 0.f, tq = 0.f;
#pragma unroll
        for (int w = 0; w < 8; w++) { ts += s_sum[w][threadIdx.x]; tq += s_sq[w][threadIdx.x]; }
        atomicAdd(&g_colsum[threadIdx.x], ts);
        atomicAdd(&g_colsq[threadIdx.x], tq);
    }
}

__global__ void k_statsfin(const float* __restrict__ ms, float inv_n) {
    int c = threadIdx.x;
    if (c < H) {
        float mean = g_colsum[c] * inv_n;
        float m2 = g_colsq[c] * inv_n;
        float msv = ms[c];
        float var = m2 - msv * (2.f - msv) * mean * mean;
        g_mean[c] = mean;
        g_invstd[c] = rsqrtf(var + EPSV);
        g_colsum[c] = 0.f;
        g_colsq[c] = 0.f;
    }
}

__global__ void k_norm_gemm(const float* __restrict__ gnw, const float* __restrict__ gnb,
                            const float* __restrict__ ms, const float* __restrict__ w2,
                            const float* __restrict__ agg, int n) {
    __shared__ float ws[H * H];
    for (int i = threadIdx.x; i < H * H; i += blockDim.x) ws[i] = w2[i];
    __syncthreads();
    int lane = threadIdx.x & 31;
    int row = (blockIdx.x * blockDim.x + threadIdx.x) >> 5;
    if (row >= n) return;
    float y = agg[row * H + lane];
    float xv = gnw[lane] * (y - ms[lane] * g_mean[lane]) * g_invstd[lane] + gnb[lane];
    xv = fmaxf(xv, 0.f);
    float acc = 0.f;
#pragma unroll
    for (int k = 0; k < H; k++)
        acc = fmaf(__shfl_sync(FULLMASK, xv, k), ws[k * H + lane], acc);
    g_h[row * H + lane] = acc;
}

__global__ void k_norm_only(const float* __restrict__ gnw, const float* __restrict__ gnb,
                            const float* __restrict__ ms, const float* __restrict__ agg, int n) {
    int lane = threadIdx.x & 31;
    int row = (blockIdx.x * blockDim.x + threadIdx.x) >> 5;
    if (row >= n) return;
    float y = agg[row * H + lane];
    float xv = gnw[lane] * (y - ms[lane] * g_mean[lane]) * g_invstd[lane] + gnb[lane];
    g_x[row * H + lane] = fmaxf(xv, 0.f);
}

// ---------------- edge MLPs (transposed float4 weights) -----------------------
__global__ void k_edge_mlp(const int* __restrict__ src, const int* __restrict__ dst,
                           const float* __restrict__ b1, const float* __restrict__ b2, int m) {
    __shared__ float4 sw1[512];   // [k4][lane]
    __shared__ float4 sw2[512];
    {
        const float4* w1f4 = reinterpret_cast<const float4*>(g_w1t);
        const float4* w2f4 = reinterpret_cast<const float4*>(g_w2t);
        for (int i = threadIdx.x; i < 512; i += blockDim.x) { sw1[i] = w1f4[i]; sw2[i] = w2f4[i]; }
    }
    __syncthreads();
    int lane = threadIdx.x & 31;
    int e = (blockIdx.x * blockDim.x + threadIdx.x) >> 5;
    if (e >= m) return;
    int s = src[e], d = dst[e];
    float xs = g_x[s * H + lane];
    float xd = g_x[d * H + lane];
    float a1 = b1[lane], a2 = b2[lane];
#pragma unroll
    for (int k4 = 0; k4 < 8; k4++) {
        float4 w1v = sw1[k4 * 32 + lane];
        float4 w2v = sw2[k4 * 32 + lane];
        float v0 = __shfl_sync(FULLMASK, xs, k4 * 4 + 0);
        float v1 = __shfl_sync(FULLMASK, xs, k4 * 4 + 1);
        float v2 = __shfl_sync(FULLMASK, xs, k4 * 4 + 2);
        float v3 = __shfl_sync(FULLMASK, xs, k4 * 4 + 3);
        a1 = fmaf(v0, w1v.x, a1); a2 = fmaf(v0, w2v.x, a2);
        a1 = fmaf(v1, w1v.y, a1); a2 = fmaf(v1, w2v.y, a2);
        a1 = fmaf(v2, w1v.z, a1); a2 = fmaf(v2, w2v.z, a2);
        a1 = fmaf(v3, w1v.w, a1); a2 = fmaf(v3, w2v.w, a2);
    }
#pragma unroll
    for (int k4 = 8; k4 < 16; k4++) {
        float4 w1v = sw1[k4 * 32 + lane];
        float4 w2v = sw2[k4 * 32 + lane];
        float v0 = __shfl_sync(FULLMASK, xd, (k4 - 8) * 4 + 0);
        float v1 = __shfl_sync(FULLMASK, xd, (k4 - 8) * 4 + 1);
        float v2 = __shfl_sync(FULLMASK, xd, (k4 - 8) * 4 + 2);
        float v3 = __shfl_sync(FULLMASK, xd, (k4 - 8) * 4 + 3);
        a1 = fmaf(v0, w1v.x, a1); a2 = fmaf(v0, w2v.x, a2);
        a1 = fmaf(v1, w1v.y, a1); a2 = fmaf(v1, w2v.y, a2);
        a1 = fmaf(v2, w1v.z, a1); a2 = fmaf(v2, w2v.z, a2);
        a1 = fmaf(v3, w1v.w, a1); a2 = fmaf(v3, w2v.w, a2);
    }
    g_xe[e * H + lane] = fmaxf(a1, 0.f);
    g_mul[e * H + lane] = fmaxf(a2, 0.f);
}

// ---------------- fused zero+scatter (per-node disjoint row ranges) -----------
// Triples are sorted by source node i; output rows are partitioned by i into
// disjoint contiguous ranges. CTA per node: zero its range, then scatter its
// own triples (atomics all land on freshly written L2 lines; no cross-CTA races).
__global__ void k_scatter_fused(const int* __restrict__ tri_a, const int* __restrict__ tri_b,
                                const int* __restrict__ tri_seg, int n, int T, int n_out) {
    int i = blockIdx.x;
    int t0, t1, rlo, rhi;
    if (i < n) {
        t0 = g_tlo[i];
        t1 = g_tlo[i + 1];
        if (t0 == t1) return;                         // no rows owned (covered by neighbors)
        rlo = (t0 == 0) ? 0 : (tri_seg[t0 - 1] + 1);
        rhi = tri_seg[t1 - 1] + 1;
    } else {                                          // tail: rows after last triple's segment
        t0 = t1 = T;
        rlo = (T == 0) ? 0 : (tri_seg[T - 1] + 1);
        rhi = n_out;
    }
    // zero owned rows
    float4* base = reinterpret_cast<float4*>(g_bmm) + (size_t)rlo * 8;
    long long nz = (long long)(rhi - rlo) * 8;
    float4 z = make_float4(0.f, 0.f, 0.f, 0.f);
    for (long long k = threadIdx.x; k < nz; k += blockDim.x) base[k] = z;
    __syncthreads();
    // scatter owned triples
    long long nt = (long long)(t1 - t0) * 8;
    for (long long k = threadIdx.x; k < nt; k += blockDim.x) {
        int t = t0 + (int)(k >> 3);
        int sub = (int)(k & 7);
        int a = tri_a[t], b = tri_b[t], sg = tri_seg[t];
        const float4 xe4 = *reinterpret_cast<const float4*>(&g_xe[a * H + sub * 4]);
        const float4 mu4 = *reinterpret_cast<const float4*>(&g_mul[b * H + sub * 4]);
        float4 p = make_float4(xe4.x * mu4.x, xe4.y * mu4.y, xe4.z * mu4.z, xe4.w * mu4.w);
        red_add_f4(&g_bmm[(size_t)sg * H + sub * 4], p);
    }
}

// ---------------- Gram accumulation (proper block reduction) ------------------
__global__ void __launch_bounds__(256) k_gram(const float* __restrict__ is_edge, int n) {
    int lane = threadIdx.x & 31;
    int wid = threadIdx.x >> 5;
    int gw = (blockIdx.x * blockDim.x + threadIdx.x) >> 5;
    int nwarps = (gridDim.x * blockDim.x) >> 5;
    int ly = lane >> 2;
    int lx = lane & 3;
    float acc[4][8];
#pragma unroll
    for (int i = 0; i < 4; i++)
#pragma unroll
        for (int j = 0; j < 8; j++) acc[i][j] = 0.f;
    float s = 0.f, w = 0.f;

    int row = gw;
    for (; row + nwarps < n; row += 2 * nwarps) {
        int r0 = row, r1 = row + nwarps;
        float v0 = g_bmm[(size_t)r0 * H + lane];
        float v1 = g_bmm[(size_t)r1 * H + lane];
        float ie0 = __ldg(&is_edge[r0]);
        float ie1 = __ldg(&is_edge[r1]);
        float ra0[4], ra1[4], cb0[8], cb1[8];
#pragma unroll
        for (int i = 0; i < 4; i++) {
            ra0[i] = __shfl_sync(FULLMASK, v0, ly * 4 + i);
            ra1[i] = __shfl_sync(FULLMASK, v1, ly * 4 + i);
        }
#pragma unroll
        for (int j = 0; j < 8; j++) {
            cb0[j] = __shfl_sync(FULLMASK, v0, lx * 8 + j);
            cb1[j] = __shfl_sync(FULLMASK, v1, lx * 8 + j);
        }
#pragma unroll
        for (int i = 0; i < 4; i++)
#pragma unroll
            for (int j = 0; j < 8; j++) {
                acc[i][j] = fmaf(ra0[i], cb0[j], acc[i][j]);
                acc[i][j] = fmaf(ra1[i], cb1[j], acc[i][j]);
            }
        s += v0 + v1;
        w = fmaf(ie0, v0, fmaf(ie1, v1, w));
    }
    for (; row < n; row += nwarps) {
        float v0 = g_bmm[(size_t)row * H + lane];
        float ie0 = __ldg(&is_edge[row]);
        float ra0[4], cb0[8];
#pragma unroll
        for (int i = 0; i < 4; i++) ra0[i] = __shfl_sync(FULLMASK, v0, ly * 4 + i);
#pragma unroll
        for (int j = 0; j < 8; j++) cb0[j] = __shfl_sync(FULLMASK, v0, lx * 8 + j);
#pragma unroll
        for (int i = 0; i < 4; i++)
#pragma unroll
            for (int j = 0; j < 8; j++) acc[i][j] = fmaf(ra0[i], cb0[j], acc[i][j]);
        s += v0;
        w = fmaf(ie0, v0, w);
    }

    // block reduction: 8 warp tiles -> shared -> 1 atomic per element per block
    __shared__ float red[8][H * H];
#pragma unroll
    for (int i = 0; i < 4; i++)
#pragma unroll
        for (int j = 0; j < 8; j++)
            red[wid][(ly * 4 + i) * H + lx * 8 + j] = acc[i][j];
    __syncthreads();
    for (int e = threadIdx.x; e < H * H; e += blockDim.x) {
        float t = 0.f;
#pragma unroll
        for (int ww = 0; ww < 8; ww++) t += red[ww][e];
        atomicAdd(&g_gram[e], t);
    }
    __syncthreads();
    // side sums
    red[wid][lane] = s;
    red[wid][H + lane] = w;
    __syncthreads();
    if (threadIdx.x < 32) {
        float ts = 0.f, tw = 0.f;
#pragma unroll
        for (int ww = 0; ww < 8; ww++) { ts += red[ww][threadIdx.x]; tw += red[ww][H + threadIdx.x]; }
        atomicAdd(&g_gs[threadIdx.x], ts);
        atomicAdd(&g_gw[threadIdx.x], tw);
    }
}

// Finisher: mean/invstd from Gram. sum(is_edge) = sum(is_edge^2) = m (0/1 values).
__global__ void k_gramfin(const float* __restrict__ w3, const float* __restrict__ b3,
                          const float* __restrict__ ms, float fn, float fm) {
    int j = threadIdx.x;
    if (j >= H) return;
    float Wc[34];
#pragma unroll 1
    for (int k = 0; k < 33; k++) Wc[k] = w3[k * H + j];
    Wc[33] = b3[j];
    float inv_n = 1.f / fn;
    double q = 0.0;
    for (int k = 0; k < 34; k++) {
        double rowdot = 0.0;
        for (int l = 0; l < 34; l++) {
            float gkl;
            if (k < 32) {
                if (l < 32) gkl = g_gram[k * H + l];
                else if (l == 32) gkl = g_gw[k];
                else gkl = g_gs[k];
            } else if (k == 32) {
                if (l < 32) gkl = g_gw[l];
                else gkl = fm;                 // (32,32)=sum ie^2=m, (32,33)=sum ie=m
            } else {
                if (l < 32) gkl = g_gs[l];
                else if (l == 32) gkl = fm;    // (33,32)=sum ie=m
                else gkl = fn;                 // (33,33)=n
            }
            rowdot += (double)gkl * (double)Wc[l];
        }
        q += (double)Wc[k] * rowdot;
    }
    double msum = 0.0;
    for (int k = 0; k < 32; k++) msum += (double)g_gs[k] * (double)Wc[k];
    msum += (double)fm * (double)Wc[32];
    msum += (double)fn * (double)Wc[33];
    float mean = (float)(msum * (double)inv_n);
    float m2 = (float)(q * (double)inv_n);
    float msv = ms[j];
    float var = m2 - msv * (2.f - msv) * mean * mean;
    g_mean[j] = mean;
    g_invstd[j] = rsqrtf(var + EPSV);
}

// ---------------- final query kernel ------------------------------------------
__device__ __forceinline__ float compute_xo(int row, int lane, const float* ws,
                                            const float* __restrict__ is_edge,
                                            const float* __restrict__ b3,
                                            const float* __restrict__ gn3w,
                                            const float* __restrict__ gn3b,
                                            const float* __restrict__ gn3ms) {
    float v = g_bmm[(size_t)row * H + lane];
    float acc = fmaf(is_edge[row], ws[32 * H + lane], b3[lane]);
#pragma unroll
    for (int k = 0; k < H; k++)
        acc = fmaf(__shfl_sync(FULLMASK, v, k), ws[k * H + lane], acc);
    float xo = gn3w[lane] * (acc - gn3ms[lane] * g_mean[lane]) * g_invstd[lane] + gn3b[lane];
    return fmaxf(xo, 0.f);
}

__global__ void k_final(const int* __restrict__ pred_idx, const int* __restrict__ trans_perm,
                        const float* __restrict__ pred_mask, const int* __restrict__ pos,
                        const float* __restrict__ is_edge,
                        const float* __restrict__ w3, const float* __restrict__ b3,
                        const float* __restrict__ gn3w, const float* __restrict__ gn3b,
                        const float* __restrict__ gn3ms,
                        const float* __restrict__ lw, const float* __restrict__ lb,
                        float* __restrict__ out, int P) {
    __shared__ float ws[33 * H];
    for (int i = threadIdx.x; i < 33 * H; i += blockDim.x) ws[i] = w3[i];
    __syncthreads();
    int lane = threadIdx.x & 31;
    int p = (blockIdx.x * blockDim.x + threadIdx.x) >> 5;
    if (p >= P) return;
    int r = pred_idx[p];
    int rt = trans_perm[r];
    float mask = pred_mask[p];
    float xo_r = compute_xo(r, lane, ws, is_edge, b3, gn3w, gn3b, gn3ms);
    float xo_t = compute_xo(rt, lane, ws, is_edge, b3, gn3w, gn3b, gn3ms);
    int i0 = pos[2 * p], j0 = pos[2 * p + 1];
    float xx = g_x[i0 * H + lane] * g_x[j0 * H + lane];
    float part = xo_r * xo_t * mask * lw[lane] + xx * lw[H + lane];
#pragma unroll
    for (int off = 16; off; off >>= 1) part += __shfl_down_sync(FULLMASK, part, off);
    if (lane == 0) out[p] = part + lb[0];
}

// ---------------- launch ------------------------------------------------------
extern "C" void kernel_launch(void* const* d_in, const int* in_sizes, int n_in,
                              void* d_out, int out_size) {
    const float* emb     = (const float*)d_in[0];
    const float* gcn1_w  = (const float*)d_in[1];
    const float* gcn1_b  = (const float*)d_in[2];
    const float* gn1_w   = (const float*)d_in[3];
    const float* gn1_b   = (const float*)d_in[4];
    const float* gn1_ms  = (const float*)d_in[5];
    const float* gcn2_w  = (const float*)d_in[6];
    const float* gcn2_b  = (const float*)d_in[7];
    const float* gn2_w   = (const float*)d_in[8];
    const float* gn2_b   = (const float*)d_in[9];
    const float* gn2_ms  = (const float*)d_in[10];
    const float* mlp1_w  = (const float*)d_in[11];
    const float* mlp1_b  = (const float*)d_in[12];
    const float* mlp2_w  = (const float*)d_in[13];
    const float* mlp2_b  = (const float*)d_in[14];
    const float* mlp3_w  = (const float*)d_in[15];
    const float* mlp3_b  = (const float*)d_in[16];
    const float* gn3_w   = (const float*)d_in[17];
    const float* gn3_b   = (const float*)d_in[18];
    const float* gn3_ms  = (const float*)d_in[19];
    const float* lind_w  = (const float*)d_in[20];
    const float* lind_b  = (const float*)d_in[21];
    const float* is_edge = (const float*)d_in[22];
    const float* pred_mask = (const float*)d_in[23];
    const int* x_nodes   = (const int*)d_in[24];
    const int* ei        = (const int*)d_in[25];
    const int* pos       = (const int*)d_in[26];
    const int* tri_a     = (const int*)d_in[27];
    const int* tri_b     = (const int*)d_in[28];
    const int* tri_seg   = (const int*)d_in[29];
    const int* trans_perm= (const int*)d_in[30];
    const int* pred_idx  = (const int*)d_in[31];

    int N     = in_sizes[24];
    int m     = in_sizes[25] / 2;
    int n_out = in_sizes[22];
    int T     = in_sizes[27];
    int P     = in_sizes[23];

    const int* src = ei;
    const int* dst = ei + m;

    int nodeWarpBlocks = (N * H + 255) / 256;
    int edgeVecBlocks = (int)(((long long)m * 8 + 255) / 256);
    int edgeWarpBlocks = (int)(((long long)m * H + 255) / 256);
    int queryWarpBlocks = (P * H + 255) / 256;

    k_zero_small<<<160, 256>>>(N);
    k_wprep<<<8, 256>>>(mlp1_w, mlp2_w);
    k_deg<<<(m + 255) / 256, 256>>>(dst, m);
    k_bounds<<<(N + 256) / 256, 256>>>(src, tri_a, N, T);

    // GCN layer 1
    k_embed_gemm<<<nodeWarpBlocks, 256>>>(emb, x_nodes, gcn1_w, N);
    k_agg<<<edgeVecBlocks, 256>>>(src, dst, g_agg, m);
    k_post<<<120, 256>>>(gcn1_b, g_agg, N);
    k_statsfin<<<1, 32>>>(gn1_ms, 1.f / (float)N);
    k_norm_gemm<<<nodeWarpBlocks, 256>>>(gn1_w, gn1_b, gn1_ms, gcn2_w, g_agg, N);

    // GCN layer 2
    k_agg<<<edgeVecBlocks, 256>>>(src, dst, g_agg2, m);
    k_post<<<120, 256>>>(gcn2_b, g_agg2, N);
    k_statsfin<<<1, 32>>>(gn2_ms, 1.f / (float)N);
    k_norm_only<<<nodeWarpBlocks, 256>>>(gn2_w, gn2_b, gn2_ms, g_agg2, N);

    // edge MLPs
    k_edge_mlp<<<edgeWarpBlocks, 256>>>(src, dst, mlp1_b, mlp2_b, m);

    // fused zero + sparse-sparse bmm scatter
    k_scatter_fused<<<N + 1, 256>>>(tri_a, tri_b, tri_seg, N, T, n_out);

    // mlp3 GraphNorm statistics via Gram (block-reduced)
    k_gram<<<592, 256>>>(is_edge, n_out);
    k_gramfin<<<1, 32>>>(mlp3_w, mlp3_b, gn3_ms, (float)n_out, (float)m);

    // final query kernel
    k_final<<<queryWarpBlocks, 256>>>(pred_idx, trans_perm, pred_mask, pos, is_edge,
                                      mlp3_w, mlp3_b, gn3_w, gn3_b, gn3_ms,
                                      lind_w, lind_b, (float*)d_out, P);
}